// round 2
// baseline (speedup 1.0000x reference)
#include <cuda_runtime.h>
#include <math.h>

#define B      64
#define HID    768
#define VOCAB  50257
#define MAXLEN 32
#define GATES  (4*HID)    // 3072
#define KCAT   (2*HID)    // 1536
#define SOS    1

#define NT 128
#define MT 64
#define KC 32

// ---------------- device-global state (no allocations allowed) ----------------
__device__ float g_h[B*HID];
__device__ float g_c[B*HID];
__device__ float g_x[B*KCAT];                       // [emb[tok] | h] per batch
__device__ float g_gates[B*GATES];
__device__ float g_Wcat[(size_t)GATES*KCAT];        // [W_ih | W_hh] per row, 18.9 MB
__device__ float g_bgate[GATES];                    // b_ih + b_hh
__device__ unsigned long long g_key[B];             // packed argmax (value,~idx)

// Monotonic float->uint mapping; low 32 bits = ~idx so ties pick the SMALLEST index.
__device__ __forceinline__ unsigned long long packKey(float v, int n) {
    unsigned u = __float_as_uint(v);
    u = (u & 0x80000000u) ? ~u : (u | 0x80000000u);
    return ((unsigned long long)u << 32) |
           (unsigned long long)(0xFFFFFFFFu - (unsigned)n);
}

// ---------------- init: build Wcat, fused bias, zero state, seed SOS ----------------
__global__ void k_init(const float* __restrict__ W_ih, const float* __restrict__ W_hh,
                       const float* __restrict__ b_ih, const float* __restrict__ b_hh) {
    int tid = blockIdx.x * blockDim.x + threadIdx.x;
    int stride = gridDim.x * blockDim.x;
    for (size_t i = tid; i < (size_t)GATES * KCAT; i += stride) {
        int j = (int)(i / KCAT);
        int k = (int)(i - (size_t)j * KCAT);
        g_Wcat[i] = (k < HID) ? W_ih[(size_t)j * HID + k]
                              : W_hh[(size_t)j * HID + (k - HID)];
    }
    for (int i = tid; i < GATES; i += stride) g_bgate[i] = b_ih[i] + b_hh[i];
    for (int i = tid; i < B * HID; i += stride) { g_h[i] = 0.f; g_c[i] = 0.f; }
    if (tid < B) g_key[tid] = (unsigned long long)(0xFFFFFFFFu - (unsigned)SOS);
}

// ---------------- prep: decode token, gather embedding, stage [x|h], zero gates ----------------
__global__ void k_prep(const float* __restrict__ emb) {
    int tid = blockIdx.x * blockDim.x + threadIdx.x;
    int stride = gridDim.x * blockDim.x;
    for (int i = tid; i < B * KCAT; i += stride) {
        int b = i / KCAT;
        int k = i - b * KCAT;
        if (k < HID) {
            int tok = (int)(0xFFFFFFFFu - (unsigned)(g_key[b] & 0xFFFFFFFFull));
            g_x[i] = emb[(size_t)tok * HID + k];
        } else {
            g_x[i] = g_h[b * HID + (k - HID)];
        }
    }
    for (int i = tid; i < B * GATES; i += stride) g_gates[i] = 0.f;
}

// ---------------- GEMM: C[64][N] = X[64][K] @ W[N][K]^T (+bias)
// mode 0: gates  (X=g_x, W=g_Wcat, split-K via atomicAdd into g_gates)
// mode 1: logits (X=g_h, W=W_out, direct store + fused argmax into g_key)
__global__ void __launch_bounds__(128) k_gemm(int mode,
        const float* __restrict__ Wp, const float* __restrict__ biasp,
        float* __restrict__ outp, long long ostridep,
        int N, int K, int kLen) {
    __shared__ __align__(16) float Xs[KC][MT + 4];
    __shared__ __align__(16) float Ws[KC][NT + 4];

    const float* X    = (mode == 0) ? g_x    : g_h;
    const float* W    = (mode == 0) ? g_Wcat : Wp;
    const float* bias = (mode == 0) ? g_bgate : biasp;
    float* out        = (mode == 0) ? g_gates : outp;
    long long ostride = (mode == 0) ? (long long)GATES : ostridep;
    int ldx           = (mode == 0) ? KCAT : HID;

    int tid = threadIdx.x;
    int mg = tid >> 4, ng = tid & 15;
    int m0 = mg * 8,   n0 = ng * 8;
    int nbase  = blockIdx.x * NT;
    int kBegin = blockIdx.y * kLen;

    float acc[8][8];
    #pragma unroll
    for (int i = 0; i < 8; i++)
        #pragma unroll
        for (int j = 0; j < 8; j++) acc[i][j] = 0.f;

    for (int kc = kBegin; kc < kBegin + kLen; kc += KC) {
        #pragma unroll
        for (int t = 0; t < (KC * MT) / 128; t++) {
            int i = tid + t * 128;
            int m = i >> 5, k = i & 31;
            Xs[k][m] = X[m * ldx + kc + k];
        }
        #pragma unroll
        for (int t = 0; t < (KC * NT) / 128; t++) {
            int i = tid + t * 128;
            int n = i >> 5, k = i & 31;
            int gn = nbase + n;
            Ws[k][n] = (gn < N) ? W[(size_t)gn * K + kc + k] : 0.f;
        }
        __syncthreads();

        #pragma unroll
        for (int k = 0; k < KC; k++) {
            float4 a0 = *reinterpret_cast<const float4*>(&Xs[k][m0]);
            float4 a1 = *reinterpret_cast<const float4*>(&Xs[k][m0 + 4]);
            float4 b0 = *reinterpret_cast<const float4*>(&Ws[k][n0]);
            float4 b1 = *reinterpret_cast<const float4*>(&Ws[k][n0 + 4]);
            float av[8] = {a0.x, a0.y, a0.z, a0.w, a1.x, a1.y, a1.z, a1.w};
            float bv[8] = {b0.x, b0.y, b0.z, b0.w, b1.x, b1.y, b1.z, b1.w};
            #pragma unroll
            for (int i = 0; i < 8; i++)
                #pragma unroll
                for (int j = 0; j < 8; j++)
                    acc[i][j] = fmaf(av[i], bv[j], acc[i][j]);
        }
        __syncthreads();
    }

    bool addBias = (mode == 1) || (blockIdx.y == 0);
    #pragma unroll
    for (int i = 0; i < 8; i++) {
        int m = m0 + i;
        unsigned long long best = 0ull;
        #pragma unroll
        for (int j = 0; j < 8; j++) {
            int n = nbase + n0 + j;
            if (n < N) {
                float v = acc[i][j] + (addBias ? bias[n] : 0.f);
                if (mode == 0) {
                    atomicAdd(&out[(long long)m * ostride + n], v);
                } else {
                    out[(long long)m * ostride + n] = v;
                    unsigned long long key = packKey(v, n);
                    if (key > best) best = key;
                }
            }
        }
        if (mode == 1) {
            // reduce across the 16 lanes sharing this m (lanes grouped within half-warps)
            #pragma unroll
            for (int s = 8; s >= 1; s >>= 1) {
                unsigned long long o = __shfl_xor_sync(0xFFFFFFFFu, best, s);
                if (o > best) best = o;
            }
            if (ng == 0) atomicMax(&g_key[m], best);
        }
    }
}

// ---------------- LSTM cell update (PyTorch gate order i,f,g,o) ----------------
__global__ void k_update() {
    int idx = blockIdx.x * blockDim.x + threadIdx.x;
    if (idx < B * HID) {
        int b = idx / HID, j = idx - b * HID;
        const float* gr = &g_gates[b * GATES];
        float iv = 1.f / (1.f + expf(-gr[j]));
        float fv = 1.f / (1.f + expf(-gr[HID + j]));
        float gv = tanhf(gr[2 * HID + j]);
        float ov = 1.f / (1.f + expf(-gr[3 * HID + j]));
        float c = fv * g_c[idx] + iv * gv;
        g_c[idx] = c;
        g_h[idx] = ov * tanhf(c);
    }
    if (idx < B) g_key[idx] = 0ull;   // reset argmax accumulator before logits GEMM
}

// ---------------- final h, c copy ----------------
__global__ void k_final(float* __restrict__ out) {
    int idx = blockIdx.x * blockDim.x + threadIdx.x;
    if (idx < B * HID) {
        out[idx]           = g_h[idx];
        out[B * HID + idx] = g_c[idx];
    }
}

extern "C" void kernel_launch(void* const* d_in, const int* in_sizes, int n_in,
                              void* d_out, int out_size) {
    // metadata order: images, emb_table, W_ih, W_hh, b_ih, b_hh, W_out, b_out
    const float* emb   = (const float*)d_in[1];
    const float* W_ih  = (const float*)d_in[2];
    const float* W_hh  = (const float*)d_in[3];
    const float* b_ih  = (const float*)d_in[4];
    const float* b_hh  = (const float*)d_in[5];
    const float* W_out = (const float*)d_in[6];
    const float* b_out = (const float*)d_in[7];
    float* out = (float*)d_out;

    k_init<<<512, 256>>>(W_ih, W_hh, b_ih, b_hh);

    const long long logitsSize = (long long)B * MAXLEN * VOCAB;
    for (int t = 0; t < MAXLEN; t++) {
        k_prep<<<192, 256>>>(emb);
        // gates: N=3072, K=1536, split-K=6 (kLen=256) for SM occupancy
        k_gemm<<<dim3(GATES / NT, 6), 128>>>(0, nullptr, nullptr, nullptr, 0,
                                             GATES, KCAT, KCAT / 6);
        k_update<<<192, 256>>>();
        // logits: N=50257, K=768, bias + argmax fused
        k_gemm<<<dim3((VOCAB + NT - 1) / NT, 1), 128>>>(1, W_out, b_out,
                out + (long long)t * VOCAB, (long long)MAXLEN * VOCAB,
                VOCAB, HID, HID);
    }
    if ((long long)out_size >= logitsSize + 2LL * B * HID)
        k_final<<<192, 256>>>(out + logitsSize);
}

// round 5
// speedup vs baseline: 1.8248x; 1.8248x over previous
#include <cuda_runtime.h>
#include <cuda_bf16.h>
#include <cstdint>
#include <math.h>

#define B      64
#define HID    768
#define VOCAB  50257
#define MAXLEN 32
#define GATES  (4*HID)
#define KCAT   (2*HID)
#define SOS    1
#define OSTRIDE ((long long)MAXLEN*VOCAB)

typedef unsigned int u32;
typedef unsigned long long u64;

// ---------------- device-global state ----------------
__device__ float g_h[B*HID];
__device__ float g_c[B*HID];
__device__ float g_gates[B*GATES];
__device__ float g_bgate[GATES];
__device__ u64   g_key[B];

// vector-accessed planes stored as uint4 for guaranteed 16B alignment
__device__ uint4 g_WhiR[((size_t)VOCAB*HID)/8];
__device__ uint4 g_WloR[((size_t)VOCAB*HID)/8];
__device__ uint4 g_WchiR[((size_t)GATES*KCAT)/8];
__device__ uint4 g_WcloR[((size_t)GATES*KCAT)/8];
__device__ uint4 g_xghiR[(B*KCAT)/8];
__device__ uint4 g_xgloR[(B*KCAT)/8];
__device__ uint4 g_hhiR[(B*HID)/8];
__device__ uint4 g_hloR[(B*HID)/8];

#define G_WHI  ((__nv_bfloat16*)g_WhiR)
#define G_WLO  ((__nv_bfloat16*)g_WloR)
#define G_WCHI ((__nv_bfloat16*)g_WchiR)
#define G_WCLO ((__nv_bfloat16*)g_WcloR)
#define G_XGHI ((__nv_bfloat16*)g_xghiR)
#define G_XGLO ((__nv_bfloat16*)g_xgloR)
#define G_HHI  ((__nv_bfloat16*)g_hhiR)
#define G_HLO  ((__nv_bfloat16*)g_hloR)

__device__ __forceinline__ void split2(float v, __nv_bfloat16* hi, __nv_bfloat16* lo) {
    __nv_bfloat16 h = __float2bfloat16_rn(v);
    *hi = h;
    *lo = __float2bfloat16_rn(v - __bfloat162float(h));
}

__device__ __forceinline__ u64 packKey(float v, int n) {
    u32 u = __float_as_uint(v);
    if (u & 0x80000000u) { u = ~u; } else { u = u | 0x80000000u; }
    u64 hi = ((u64)u) << 32;
    u64 lo = (u64)(0xFFFFFFFFu - (u32)n);
    return hi | lo;
}

__device__ __forceinline__ void ldsm4(u32* r, const __nv_bfloat16* p) {
    u32 a = (u32)__cvta_generic_to_shared(p);
    asm volatile("ldmatrix.sync.aligned.m8n8.x4.shared.b16 {%0,%1,%2,%3},[%4];"
                 : "=r"(r[0]), "=r"(r[1]), "=r"(r[2]), "=r"(r[3]) : "r"(a));
}

__device__ __forceinline__ void mma16816(float* d, const u32* a, u32 b0, u32 b1) {
    asm volatile("mma.sync.aligned.m16n8k16.row.col.f32.bf16.bf16.f32 "
                 "{%0,%1,%2,%3},{%4,%5,%6,%7},{%8,%9},{%0,%1,%2,%3};"
                 : "+f"(d[0]), "+f"(d[1]), "+f"(d[2]), "+f"(d[3])
                 : "r"(a[0]), "r"(a[1]), "r"(a[2]), "r"(a[3]), "r"(b0), "r"(b1));
}

// ---------------- init ----------------
__global__ void k_init(const float* __restrict__ W_ih, const float* __restrict__ W_hh,
                       const float* __restrict__ b_ih, const float* __restrict__ b_hh,
                       const float* __restrict__ W_out) {
    size_t tid = (size_t)blockIdx.x * blockDim.x + threadIdx.x;
    size_t stride = (size_t)gridDim.x * blockDim.x;
    for (size_t i = tid; i < (size_t)VOCAB * HID; i += stride) {
        split2(W_out[i], &G_WHI[i], &G_WLO[i]);
    }
    for (size_t i = tid; i < (size_t)GATES * KCAT; i += stride) {
        int j = (int)(i / KCAT);
        int k = (int)(i - (size_t)j * KCAT);
        float v;
        if (k < HID) { v = W_ih[(size_t)j * HID + k]; }
        else         { v = W_hh[(size_t)j * HID + (k - HID)]; }
        split2(v, &G_WCHI[i], &G_WCLO[i]);
    }
    for (size_t i = tid; i < GATES; i += stride) {
        g_bgate[i] = b_ih[i] + b_hh[i];
    }
    for (size_t i = tid; i < B * HID; i += stride) {
        g_h[i] = 0.f;
        g_c[i] = 0.f;
    }
    if (tid < B) {
        g_key[tid] = (u64)(0xFFFFFFFFu - (u32)SOS);
    }
}

// ---------------- prep: token -> [emb|h] split planes, zero gates ----------------
__global__ void k_prep(const float* __restrict__ emb) {
    int tid = blockIdx.x * blockDim.x + threadIdx.x;
    int stride = gridDim.x * blockDim.x;
    for (int i = tid; i < B * KCAT; i += stride) {
        int b = i / KCAT;
        int k = i - b * KCAT;
        float v;
        if (k < HID) {
            int tok = (int)(0xFFFFFFFFu - (u32)(g_key[b] & 0xFFFFFFFFull));
            v = emb[(size_t)tok * HID + k];
        } else {
            v = g_h[b * HID + (k - HID)];
        }
        split2(v, &G_XGHI[i], &G_XGLO[i]);
    }
    for (int i = tid; i < B * GATES; i += stride) {
        g_gates[i] = 0.f;
    }
}

// ---------------- logits GEMM + fused bias/argmax ----------------
// C[64][VOCAB] = h @ W_out^T + b ; block tile N=256 (8 warps x 32), M=64
__global__ void __launch_bounds__(256) k_logits(const float* __restrict__ bias,
                                                float* __restrict__ outStep) {
    __shared__ uint4 XsRaw[(2 * 64 * 40) / 8];   // plane p, row r: bf16 idx p*2560+r*40+c
    __shared__ u64 skey[64];
    __nv_bfloat16* Xs = (__nv_bfloat16*)XsRaw;

    int tid = threadIdx.x;
    int w = tid >> 5;
    int l = tid & 31;
    int nwarp = blockIdx.x * 256 + w * 32;

    if (tid < 64) { skey[tid] = 0ull; }

    float acc[4][4][4];
    #pragma unroll
    for (int i = 0; i < 4; i++) {
        #pragma unroll
        for (int j = 0; j < 4; j++) {
            #pragma unroll
            for (int q = 0; q < 4; q++) { acc[i][j][q] = 0.f; }
        }
    }

    int lm = tid >> 2;                 // 0..63 cooperative-load row
    int lk = (tid & 3) * 8;            // 0..24 col offset (8 bf16 = 1 uint4)
    int sub = l >> 3;
    int arow = (sub & 1) * 8 + (l & 7);
    int acolo = (sub >> 1) * 8;

    for (int kc = 0; kc < HID; kc += 32) {
        {
            const uint4* sh = reinterpret_cast<const uint4*>(&G_HHI[lm * HID + kc + lk]);
            const uint4* sl = reinterpret_cast<const uint4*>(&G_HLO[lm * HID + kc + lk]);
            XsRaw[lm * 5 + (lk >> 3)] = sh[0];
            XsRaw[320 + lm * 5 + (lk >> 3)] = sl[0];
        }
        __syncthreads();
        #pragma unroll
        for (int kk = 0; kk < 2; kk++) {
            int kb = kk * 16;
            u32 ahi[4][4];
            u32 alo[4][4];
            #pragma unroll
            for (int mt = 0; mt < 4; mt++) {
                ldsm4(ahi[mt], &Xs[(mt * 16 + arow) * 40 + kb + acolo]);
                ldsm4(alo[mt], &Xs[2560 + (mt * 16 + arow) * 40 + kb + acolo]);
            }
            int gk = kc + kb + (l & 3) * 2;
            #pragma unroll
            for (int nt = 0; nt < 4; nt++) {
                int n = nwarp + nt * 8 + (l >> 2);
                if (n >= VOCAB) { n = VOCAB - 1; }
                const u32* ph = reinterpret_cast<const u32*>(&G_WHI[(size_t)n * HID + gk]);
                const u32* pl = reinterpret_cast<const u32*>(&G_WLO[(size_t)n * HID + gk]);
                u32 bh0 = ph[0];
                u32 bh1 = ph[4];
                u32 bl0 = pl[0];
                u32 bl1 = pl[4];
                #pragma unroll
                for (int mt = 0; mt < 4; mt++) {
                    mma16816(acc[mt][nt], ahi[mt], bh0, bh1);
                    mma16816(acc[mt][nt], ahi[mt], bl0, bl1);
                    mma16816(acc[mt][nt], alo[mt], bh0, bh1);
                }
            }
        }
        __syncthreads();
    }

    // epilogue: bias + store + argmax keys
    #pragma unroll
    for (int mt = 0; mt < 4; mt++) {
        int r = mt * 16 + (l >> 2);
        u64 k0 = 0ull;
        u64 k1 = 0ull;
        #pragma unroll
        for (int nt = 0; nt < 4; nt++) {
            int c0 = nwarp + nt * 8 + (l & 3) * 2;
            if (c0 + 1 < VOCAB) {
                const float2* bp = reinterpret_cast<const float2*>(&bias[c0]);
                float2 bb = bp[0];
                float v0 = acc[mt][nt][0] + bb.x;
                float v1 = acc[mt][nt][1] + bb.y;
                float v2 = acc[mt][nt][2] + bb.x;
                float v3 = acc[mt][nt][3] + bb.y;
                outStep[(long long)r * OSTRIDE + c0]           = v0;
                outStep[(long long)r * OSTRIDE + c0 + 1]       = v1;
                outStep[(long long)(r + 8) * OSTRIDE + c0]     = v2;
                outStep[(long long)(r + 8) * OSTRIDE + c0 + 1] = v3;
                u64 t;
                t = packKey(v0, c0);     if (t > k0) { k0 = t; }
                t = packKey(v1, c0 + 1); if (t > k0) { k0 = t; }
                t = packKey(v2, c0);     if (t > k1) { k1 = t; }
                t = packKey(v3, c0 + 1); if (t > k1) { k1 = t; }
            } else if (c0 < VOCAB) {
                float bb = bias[c0];
                float v0 = acc[mt][nt][0] + bb;
                float v2 = acc[mt][nt][2] + bb;
                outStep[(long long)r * OSTRIDE + c0]       = v0;
                outStep[(long long)(r + 8) * OSTRIDE + c0] = v2;
                u64 t;
                t = packKey(v0, c0); if (t > k0) { k0 = t; }
                t = packKey(v2, c0); if (t > k1) { k1 = t; }
            }
        }
        #pragma unroll
        for (int s = 1; s <= 2; s <<= 1) {
            u64 o0 = __shfl_xor_sync(0xFFFFFFFFu, k0, s);
            u64 o1 = __shfl_xor_sync(0xFFFFFFFFu, k1, s);
            if (o0 > k0) { k0 = o0; }
            if (o1 > k1) { k1 = o1; }
        }
        if ((l & 3) == 0) {
            atomicMax(&skey[r], k0);
            atomicMax(&skey[r + 8], k1);
        }
    }
    __syncthreads();
    if (tid < 64) {
        if (skey[tid] != 0ull) { atomicMax(&g_key[tid], skey[tid]); }
    }
}

// ---------------- gates GEMM: g_gates[64][3072] += x @ Wcat^T (+b on split 0) ----------------
__global__ void __launch_bounds__(256) k_gates() {
    __shared__ uint4 XsRaw[(2 * 64 * 40) / 8];
    __nv_bfloat16* Xs = (__nv_bfloat16*)XsRaw;

    int tid = threadIdx.x;
    int w = tid >> 5;
    int l = tid & 31;
    int nwarp = blockIdx.x * 128 + w * 16;     // 8 warps x 16 cols = 128
    int kBegin = blockIdx.y * 192;

    float acc[4][2][4];
    #pragma unroll
    for (int i = 0; i < 4; i++) {
        #pragma unroll
        for (int j = 0; j < 2; j++) {
            #pragma unroll
            for (int q = 0; q < 4; q++) { acc[i][j][q] = 0.f; }
        }
    }

    int lm = tid >> 2;
    int lk = (tid & 3) * 8;
    int sub = l >> 3;
    int arow = (sub & 1) * 8 + (l & 7);
    int acolo = (sub >> 1) * 8;

    for (int kc = kBegin; kc < kBegin + 192; kc += 32) {
        {
            const uint4* sh = reinterpret_cast<const uint4*>(&G_XGHI[lm * KCAT + kc + lk]);
            const uint4* sl = reinterpret_cast<const uint4*>(&G_XGLO[lm * KCAT + kc + lk]);
            XsRaw[lm * 5 + (lk >> 3)] = sh[0];
            XsRaw[320 + lm * 5 + (lk >> 3)] = sl[0];
        }
        __syncthreads();
        #pragma unroll
        for (int kk = 0; kk < 2; kk++) {
            int kb = kk * 16;
            u32 ahi[4][4];
            u32 alo[4][4];
            #pragma unroll
            for (int mt = 0; mt < 4; mt++) {
                ldsm4(ahi[mt], &Xs[(mt * 16 + arow) * 40 + kb + acolo]);
                ldsm4(alo[mt], &Xs[2560 + (mt * 16 + arow) * 40 + kb + acolo]);
            }
            int gk = kc + kb + (l & 3) * 2;
            #pragma unroll
            for (int nt = 0; nt < 2; nt++) {
                int n = nwarp + nt * 8 + (l >> 2);
                const u32* ph = reinterpret_cast<const u32*>(&G_WCHI[(size_t)n * KCAT + gk]);
                const u32* pl = reinterpret_cast<const u32*>(&G_WCLO[(size_t)n * KCAT + gk]);
                u32 bh0 = ph[0];
                u32 bh1 = ph[4];
                u32 bl0 = pl[0];
                u32 bl1 = pl[4];
                #pragma unroll
                for (int mt = 0; mt < 4; mt++) {
                    mma16816(acc[mt][nt], ahi[mt], bh0, bh1);
                    mma16816(acc[mt][nt], ahi[mt], bl0, bl1);
                    mma16816(acc[mt][nt], alo[mt], bh0, bh1);
                }
            }
        }
        __syncthreads();
    }

    bool ab = (blockIdx.y == 0);
    #pragma unroll
    for (int mt = 0; mt < 4; mt++) {
        int r = mt * 16 + (l >> 2);
        #pragma unroll
        for (int nt = 0; nt < 2; nt++) {
            int c0 = nwarp + nt * 8 + (l & 3) * 2;
            float bb0 = 0.f;
            float bb1 = 0.f;
            if (ab) { bb0 = g_bgate[c0]; bb1 = g_bgate[c0 + 1]; }
            atomicAdd(&g_gates[r * GATES + c0],           acc[mt][nt][0] + bb0);
            atomicAdd(&g_gates[r * GATES + c0 + 1],       acc[mt][nt][1] + bb1);
            atomicAdd(&g_gates[(r + 8) * GATES + c0],     acc[mt][nt][2] + bb0);
            atomicAdd(&g_gates[(r + 8) * GATES + c0 + 1], acc[mt][nt][3] + bb1);
        }
    }
}

// ---------------- LSTM cell update + argmax-accumulator reset ----------------
__global__ void k_update() {
    int idx = blockIdx.x * blockDim.x + threadIdx.x;
    if (idx < B * HID) {
        int b = idx / HID;
        int j = idx - b * HID;
        const float* gr = &g_gates[b * GATES];
        float iv = 1.f / (1.f + expf(-gr[j]));
        float fv = 1.f / (1.f + expf(-gr[HID + j]));
        float gv = tanhf(gr[2 * HID + j]);
        float ov = 1.f / (1.f + expf(-gr[3 * HID + j]));
        float c = fv * g_c[idx] + iv * gv;
        float h = ov * tanhf(c);
        g_c[idx] = c;
        g_h[idx] = h;
        split2(h, &G_HHI[idx], &G_HLO[idx]);
    }
    if (idx < B) {
        g_key[idx] = 0ull;
    }
}

__global__ void k_final(float* __restrict__ out) {
    int idx = blockIdx.x * blockDim.x + threadIdx.x;
    if (idx < B * HID) {
        out[idx]           = g_h[idx];
        out[B * HID + idx] = g_c[idx];
    }
}

extern "C" void kernel_launch(void* const* d_in, const int* in_sizes, int n_in,
                              void* d_out, int out_size) {
    const float* emb   = (const float*)d_in[1];
    const float* W_ih  = (const float*)d_in[2];
    const float* W_hh  = (const float*)d_in[3];
    const float* b_ih  = (const float*)d_in[4];
    const float* b_hh  = (const float*)d_in[5];
    const float* W_out = (const float*)d_in[6];
    const float* b_out = (const float*)d_in[7];
    float* out = (float*)d_out;

    k_init<<<2048, 256>>>(W_ih, W_hh, b_ih, b_hh, W_out);

    const long long logitsSize = (long long)B * MAXLEN * VOCAB;
    for (int t = 0; t < MAXLEN; t++) {
        k_prep<<<192, 256>>>(emb);
        k_gates<<<dim3(GATES / 128, 8), 256>>>();
        k_update<<<192, 256>>>();
        k_logits<<<(VOCAB + 255) / 256, 256>>>(b_out, out + (long long)t * VOCAB);
    }
    if ((long long)out_size >= logitsSize + 2LL * B * HID) {
        k_final<<<192, 256>>>(out + logitsSize);
    }
}

// round 6
// speedup vs baseline: 3.1551x; 1.7290x over previous
#include <cuda_runtime.h>
#include <cuda_bf16.h>
#include <cstdint>
#include <math.h>

#define B      64
#define HID    768
#define VOCAB  50257
#define MAXLEN 32
#define GATES  (4*HID)
#define KCAT   (2*HID)
#define SOS    1
#define OSTRIDE ((long long)MAXLEN*VOCAB)

typedef unsigned int u32;
typedef unsigned long long u64;

// ---------------- device-global state ----------------
__device__ float g_h[B*HID];
__device__ float g_c[B*HID];
__device__ float g_gates[B*GATES];
__device__ float g_bgate[GATES];
__device__ u64   g_key[B];

__device__ uint4 g_WhiR[((size_t)VOCAB*HID)/8];
__device__ uint4 g_WloR[((size_t)VOCAB*HID)/8];
__device__ uint4 g_WchiR[((size_t)GATES*KCAT)/8];
__device__ uint4 g_WcloR[((size_t)GATES*KCAT)/8];
__device__ uint4 g_hhiR[(B*HID)/8];
__device__ uint4 g_hloR[(B*HID)/8];

#define G_WHI  ((__nv_bfloat16*)g_WhiR)
#define G_WLO  ((__nv_bfloat16*)g_WloR)
#define G_WCHI ((__nv_bfloat16*)g_WchiR)
#define G_WCLO ((__nv_bfloat16*)g_WcloR)
#define G_HHI  ((__nv_bfloat16*)g_hhiR)
#define G_HLO  ((__nv_bfloat16*)g_hloR)

__device__ __forceinline__ void split2(float v, __nv_bfloat16* hi, __nv_bfloat16* lo) {
    __nv_bfloat16 h = __float2bfloat16_rn(v);
    *hi = h;
    *lo = __float2bfloat16_rn(v - __bfloat162float(h));
}

__device__ __forceinline__ u64 packKey(float v, int n) {
    u32 u = __float_as_uint(v);
    if (u & 0x80000000u) { u = ~u; } else { u = u | 0x80000000u; }
    return (((u64)u) << 32) | (u64)(0xFFFFFFFFu - (u32)n);
}

__device__ __forceinline__ void ldsm4(u32* r, const __nv_bfloat16* p) {
    u32 a = (u32)__cvta_generic_to_shared(p);
    asm volatile("ldmatrix.sync.aligned.m8n8.x4.shared.b16 {%0,%1,%2,%3},[%4];"
                 : "=r"(r[0]), "=r"(r[1]), "=r"(r[2]), "=r"(r[3]) : "r"(a));
}

__device__ __forceinline__ void mma16816(float* d, const u32* a, u32 b0, u32 b1) {
    asm volatile("mma.sync.aligned.m16n8k16.row.col.f32.bf16.bf16.f32 "
                 "{%0,%1,%2,%3},{%4,%5,%6,%7},{%8,%9},{%0,%1,%2,%3};"
                 : "+f"(d[0]), "+f"(d[1]), "+f"(d[2]), "+f"(d[3])
                 : "r"(a[0]), "r"(a[1]), "r"(a[2]), "r"(a[3]), "r"(b0), "r"(b1));
}

// ---------------- init ----------------
__global__ void k_init(const float* __restrict__ W_ih, const float* __restrict__ W_hh,
                       const float* __restrict__ b_ih, const float* __restrict__ b_hh,
                       const float* __restrict__ W_out) {
    size_t tid = (size_t)blockIdx.x * blockDim.x + threadIdx.x;
    size_t stride = (size_t)gridDim.x * blockDim.x;
    for (size_t i = tid; i < (size_t)VOCAB * HID; i += stride) {
        split2(W_out[i], &G_WHI[i], &G_WLO[i]);
    }
    for (size_t i = tid; i < (size_t)GATES * KCAT; i += stride) {
        int j = (int)(i / KCAT);
        int k = (int)(i - (size_t)j * KCAT);
        float v;
        if (k < HID) { v = W_ih[(size_t)j * HID + k]; }
        else         { v = W_hh[(size_t)j * HID + (k - HID)]; }
        split2(v, &G_WCHI[i], &G_WCLO[i]);
    }
    for (size_t i = tid; i < GATES; i += stride) { g_bgate[i] = b_ih[i] + b_hh[i]; }
    for (size_t i = tid; i < B * HID; i += stride) { g_h[i] = 0.f; g_c[i] = 0.f; }
    for (size_t i = tid; i < (size_t)B * GATES; i += stride) { g_gates[i] = 0.f; }
    if (tid < B) { g_key[tid] = (u64)(0xFFFFFFFFu - (u32)SOS); }
}

// ================= logits GEMM helpers (nt=3) =================
__device__ __forceinline__ void loadw3(u32 (&wb)[3][2][4], const u32* Whi32, const u32* Wlo32,
                                       const size_t (&wrow)[3], int kc) {
    int kw = kc >> 1;
    #pragma unroll
    for (int nt = 0; nt < 3; nt++) {
        const u32* ph = Whi32 + wrow[nt] + kw;
        const u32* pl = Wlo32 + wrow[nt] + kw;
        wb[nt][0][0] = ph[0]; wb[nt][0][1] = ph[4]; wb[nt][0][2] = ph[8]; wb[nt][0][3] = ph[12];
        wb[nt][1][0] = pl[0]; wb[nt][1][1] = pl[4]; wb[nt][1][2] = pl[8]; wb[nt][1][3] = pl[12];
    }
}

__device__ __forceinline__ void do_chunk3(float (&acc)[4][3][4], const u32 (&wb)[3][2][4],
                                          const __nv_bfloat16* Xs, int stg, int arow, int acolo) {
    #pragma unroll
    for (int kk = 0; kk < 2; kk++) {
        int kb = kk * 16;
        u32 ahi[4][4];
        u32 alo[4][4];
        #pragma unroll
        for (int mt = 0; mt < 4; mt++) {
            ldsm4(ahi[mt], &Xs[(stg * 2 + 0) * 2560 + (mt * 16 + arow) * 40 + kb + acolo]);
            ldsm4(alo[mt], &Xs[(stg * 2 + 1) * 2560 + (mt * 16 + arow) * 40 + kb + acolo]);
        }
        #pragma unroll
        for (int nt = 0; nt < 3; nt++) {
            u32 bh0 = wb[nt][0][2 * kk];
            u32 bh1 = wb[nt][0][2 * kk + 1];
            u32 bl0 = wb[nt][1][2 * kk];
            u32 bl1 = wb[nt][1][2 * kk + 1];
            #pragma unroll
            for (int mt = 0; mt < 4; mt++) {
                mma16816(acc[mt][nt], ahi[mt], bh0, bh1);
                mma16816(acc[mt][nt], ahi[mt], bl0, bl1);
                mma16816(acc[mt][nt], alo[mt], bh0, bh1);
            }
        }
    }
}

// ---------------- logits: C[64][VOCAB] = h @ W_out^T + b, fused argmax ----------------
// block N-tile 192 (8 warps x 24), double-buffered X stage + register W prefetch
__global__ void __launch_bounds__(256, 1) k_logits(const float* __restrict__ bias,
                                                   float* __restrict__ outStep) {
    __shared__ uint4 XsRaw[1280];     // 2 stages x 2 planes x 320 uint4
    __shared__ u64 skey[64];
    const __nv_bfloat16* Xs = (const __nv_bfloat16*)XsRaw;

    int tid = threadIdx.x;
    int w = tid >> 5;
    int l = tid & 31;
    int nwarp = blockIdx.x * 192 + w * 24;
    if (tid < 64) { skey[tid] = 0ull; }

    int lm = tid >> 2;
    int lk = (tid & 3) * 8;
    int sub = l >> 3;
    int arow = (sub & 1) * 8 + (l & 7);
    int acolo = (sub >> 1) * 8;

    const u32* Whi32 = (const u32*)g_WhiR;
    const u32* Wlo32 = (const u32*)g_WloR;
    size_t wrow[3];
    #pragma unroll
    for (int nt = 0; nt < 3; nt++) {
        int n = nwarp + nt * 8 + (l >> 2);
        if (n >= VOCAB) { n = VOCAB - 1; }
        wrow[nt] = (size_t)n * (HID / 2) + (l & 3);
    }

    float acc[4][3][4];
    #pragma unroll
    for (int i = 0; i < 4; i++) {
        #pragma unroll
        for (int j = 0; j < 3; j++) {
            #pragma unroll
            for (int q = 0; q < 4; q++) { acc[i][j][q] = 0.f; }
        }
    }

    u32 wa[3][2][4];
    u32 wb[3][2][4];
    int sidx = lm * 5 + (lk >> 3);

    // prologue: stage chunk 0, load W chunk 0
    XsRaw[0 * 320 + sidx] = *reinterpret_cast<const uint4*>(&G_HHI[lm * HID + lk]);
    XsRaw[1 * 320 + sidx] = *reinterpret_cast<const uint4*>(&G_HLO[lm * HID + lk]);
    loadw3(wa, Whi32, Wlo32, wrow, 0);
    __syncthreads();

    #pragma unroll 1
    for (int it = 0; it < 24; it += 2) {
        int kn1 = (it + 1) * 32;
        uint4 xh1 = *reinterpret_cast<const uint4*>(&G_HHI[lm * HID + kn1 + lk]);
        uint4 xl1 = *reinterpret_cast<const uint4*>(&G_HLO[lm * HID + kn1 + lk]);
        loadw3(wb, Whi32, Wlo32, wrow, kn1);
        do_chunk3(acc, wa, Xs, 0, arow, acolo);
        XsRaw[2 * 320 + sidx] = xh1;
        XsRaw[3 * 320 + sidx] = xl1;
        __syncthreads();

        int kn2 = (it < 22) ? (it + 2) * 32 : 736;
        uint4 xh2 = *reinterpret_cast<const uint4*>(&G_HHI[lm * HID + kn2 + lk]);
        uint4 xl2 = *reinterpret_cast<const uint4*>(&G_HLO[lm * HID + kn2 + lk]);
        loadw3(wa, Whi32, Wlo32, wrow, kn2);
        do_chunk3(acc, wb, Xs, 1, arow, acolo);
        XsRaw[0 * 320 + sidx] = xh2;
        XsRaw[1 * 320 + sidx] = xl2;
        __syncthreads();
    }

    // epilogue: bias + store + argmax keys
    #pragma unroll
    for (int mt = 0; mt < 4; mt++) {
        int r = mt * 16 + (l >> 2);
        u64 k0 = 0ull;
        u64 k1 = 0ull;
        #pragma unroll
        for (int nt = 0; nt < 3; nt++) {
            int c0 = nwarp + nt * 8 + (l & 3) * 2;
            if (c0 + 1 < VOCAB) {
                const float2* bp = reinterpret_cast<const float2*>(&bias[c0]);
                float2 bb = bp[0];
                float v0 = acc[mt][nt][0] + bb.x;
                float v1 = acc[mt][nt][1] + bb.y;
                float v2 = acc[mt][nt][2] + bb.x;
                float v3 = acc[mt][nt][3] + bb.y;
                outStep[(long long)r * OSTRIDE + c0]           = v0;
                outStep[(long long)r * OSTRIDE + c0 + 1]       = v1;
                outStep[(long long)(r + 8) * OSTRIDE + c0]     = v2;
                outStep[(long long)(r + 8) * OSTRIDE + c0 + 1] = v3;
                u64 t;
                t = packKey(v0, c0);     if (t > k0) { k0 = t; }
                t = packKey(v1, c0 + 1); if (t > k0) { k0 = t; }
                t = packKey(v2, c0);     if (t > k1) { k1 = t; }
                t = packKey(v3, c0 + 1); if (t > k1) { k1 = t; }
            } else if (c0 < VOCAB) {
                float bb = bias[c0];
                float v0 = acc[mt][nt][0] + bb;
                float v2 = acc[mt][nt][2] + bb;
                outStep[(long long)r * OSTRIDE + c0]       = v0;
                outStep[(long long)(r + 8) * OSTRIDE + c0] = v2;
                u64 t;
                t = packKey(v0, c0); if (t > k0) { k0 = t; }
                t = packKey(v2, c0); if (t > k1) { k1 = t; }
            }
        }
        #pragma unroll
        for (int s = 1; s <= 2; s <<= 1) {
            u64 o0 = __shfl_xor_sync(0xFFFFFFFFu, k0, s);
            u64 o1 = __shfl_xor_sync(0xFFFFFFFFu, k1, s);
            if (o0 > k0) { k0 = o0; }
            if (o1 > k1) { k1 = o1; }
        }
        if ((l & 3) == 0) {
            atomicMax(&skey[r], k0);
            atomicMax(&skey[r + 8], k1);
        }
    }
    __syncthreads();
    if (tid < 64) {
        if (skey[tid] != 0ull) { atomicMax(&g_key[tid], skey[tid]); }
    }
}

// ================= gates GEMM helpers (nt=2) =================
__device__ __forceinline__ void loadw2(u32 (&wb)[2][2][4], const u32* Whi32, const u32* Wlo32,
                                       const size_t (&wrow)[2], int kc) {
    int kw = kc >> 1;
    #pragma unroll
    for (int nt = 0; nt < 2; nt++) {
        const u32* ph = Whi32 + wrow[nt] + kw;
        const u32* pl = Wlo32 + wrow[nt] + kw;
        wb[nt][0][0] = ph[0]; wb[nt][0][1] = ph[4]; wb[nt][0][2] = ph[8]; wb[nt][0][3] = ph[12];
        wb[nt][1][0] = pl[0]; wb[nt][1][1] = pl[4]; wb[nt][1][2] = pl[8]; wb[nt][1][3] = pl[12];
    }
}

__device__ __forceinline__ void do_chunk2(float (&acc)[4][2][4], const u32 (&wb)[2][2][4],
                                          const __nv_bfloat16* Xs, int stg, int arow, int acolo) {
    #pragma unroll
    for (int kk = 0; kk < 2; kk++) {
        int kb = kk * 16;
        u32 ahi[4][4];
        u32 alo[4][4];
        #pragma unroll
        for (int mt = 0; mt < 4; mt++) {
            ldsm4(ahi[mt], &Xs[(stg * 2 + 0) * 2560 + (mt * 16 + arow) * 40 + kb + acolo]);
            ldsm4(alo[mt], &Xs[(stg * 2 + 1) * 2560 + (mt * 16 + arow) * 40 + kb + acolo]);
        }
        #pragma unroll
        for (int nt = 0; nt < 2; nt++) {
            u32 bh0 = wb[nt][0][2 * kk];
            u32 bh1 = wb[nt][0][2 * kk + 1];
            u32 bl0 = wb[nt][1][2 * kk];
            u32 bl1 = wb[nt][1][2 * kk + 1];
            #pragma unroll
            for (int mt = 0; mt < 4; mt++) {
                mma16816(acc[mt][nt], ahi[mt], bh0, bh1);
                mma16816(acc[mt][nt], ahi[mt], bl0, bl1);
                mma16816(acc[mt][nt], alo[mt], bh0, bh1);
            }
        }
    }
}

// gather x[b][k] = (k<HID ? emb[tok[b]][k] : h[b][k-HID]) and split into bf16 hi/lo uint4
__device__ __forceinline__ void gatherx(int lm, int lk, int kc, const float* __restrict__ emb,
                                        const int* stoks, uint4& xh, uint4& xl) {
    int k = kc + lk;
    const float* src;
    if (k < HID) { src = emb + (size_t)stoks[lm] * HID + k; }
    else         { src = g_h + lm * HID + (k - HID); }
    float4 f0 = *reinterpret_cast<const float4*>(src);
    float4 f1 = *reinterpret_cast<const float4*>(src + 4);
    float v[8] = {f0.x, f0.y, f0.z, f0.w, f1.x, f1.y, f1.z, f1.w};
    u32 hw[4];
    u32 lw[4];
    #pragma unroll
    for (int e = 0; e < 4; e++) {
        __nv_bfloat16 h0, l0, h1, l1;
        split2(v[2 * e], &h0, &l0);
        split2(v[2 * e + 1], &h1, &l1);
        __nv_bfloat162 hp;
        hp.x = h0; hp.y = h1;
        __nv_bfloat162 lp;
        lp.x = l0; lp.y = l1;
        hw[e] = *reinterpret_cast<u32*>(&hp);
        lw[e] = *reinterpret_cast<u32*>(&lp);
    }
    xh = make_uint4(hw[0], hw[1], hw[2], hw[3]);
    xl = make_uint4(lw[0], lw[1], lw[2], lw[3]);
}

// ---------------- gates: g_gates[64][3072] += [emb|h] @ Wcat^T (+b on split 0) ----------------
__global__ void __launch_bounds__(256, 1) k_gates(const float* __restrict__ emb) {
    __shared__ uint4 XsRaw[1280];
    __shared__ int stoks[64];
    const __nv_bfloat16* Xs = (const __nv_bfloat16*)XsRaw;

    int tid = threadIdx.x;
    int w = tid >> 5;
    int l = tid & 31;
    int nwarp = blockIdx.x * 128 + w * 16;
    int kBegin = blockIdx.y * 192;

    if (tid < 64) {
        stoks[tid] = (int)(0xFFFFFFFFu - (u32)(g_key[tid] & 0xFFFFFFFFull));
    }
    __syncthreads();

    int lm = tid >> 2;
    int lk = (tid & 3) * 8;
    int sub = l >> 3;
    int arow = (sub & 1) * 8 + (l & 7);
    int acolo = (sub >> 1) * 8;

    const u32* Whi32 = (const u32*)g_WchiR;
    const u32* Wlo32 = (const u32*)g_WcloR;
    size_t wrow[2];
    #pragma unroll
    for (int nt = 0; nt < 2; nt++) {
        int n = nwarp + nt * 8 + (l >> 2);
        wrow[nt] = (size_t)n * (KCAT / 2) + (l & 3);
    }

    float acc[4][2][4];
    #pragma unroll
    for (int i = 0; i < 4; i++) {
        #pragma unroll
        for (int j = 0; j < 2; j++) {
            #pragma unroll
            for (int q = 0; q < 4; q++) { acc[i][j][q] = 0.f; }
        }
    }

    u32 wa[2][2][4];
    u32 wb[2][2][4];
    int sidx = lm * 5 + (lk >> 3);

    {
        uint4 xh0, xl0;
        gatherx(lm, lk, kBegin, emb, stoks, xh0, xl0);
        XsRaw[0 * 320 + sidx] = xh0;
        XsRaw[1 * 320 + sidx] = xl0;
    }
    loadw2(wa, Whi32, Wlo32, wrow, kBegin);
    __syncthreads();

    #pragma unroll 1
    for (int it = 0; it < 6; it += 2) {
        int kn1 = kBegin + (it + 1) * 32;
        uint4 xh1, xl1;
        gatherx(lm, lk, kn1, emb, stoks, xh1, xl1);
        loadw2(wb, Whi32, Wlo32, wrow, kn1);
        do_chunk2(acc, wa, Xs, 0, arow, acolo);
        XsRaw[2 * 320 + sidx] = xh1;
        XsRaw[3 * 320 + sidx] = xl1;
        __syncthreads();

        int kn2 = (it < 4) ? kBegin + (it + 2) * 32 : kBegin + 160;
        uint4 xh2, xl2;
        gatherx(lm, lk, kn2, emb, stoks, xh2, xl2);
        loadw2(wa, Whi32, Wlo32, wrow, kn2);
        do_chunk2(acc, wb, Xs, 1, arow, acolo);
        XsRaw[0 * 320 + sidx] = xh2;
        XsRaw[1 * 320 + sidx] = xl2;
        __syncthreads();
    }

    bool ab = (blockIdx.y == 0);
    #pragma unroll
    for (int mt = 0; mt < 4; mt++) {
        int r = mt * 16 + (l >> 2);
        #pragma unroll
        for (int nt = 0; nt < 2; nt++) {
            int c0 = nwarp + nt * 8 + (l & 3) * 2;
            float bb0 = 0.f;
            float bb1 = 0.f;
            if (ab) { bb0 = g_bgate[c0]; bb1 = g_bgate[c0 + 1]; }
            atomicAdd(&g_gates[r * GATES + c0],           acc[mt][nt][0] + bb0);
            atomicAdd(&g_gates[r * GATES + c0 + 1],       acc[mt][nt][1] + bb1);
            atomicAdd(&g_gates[(r + 8) * GATES + c0],     acc[mt][nt][2] + bb0);
            atomicAdd(&g_gates[(r + 8) * GATES + c0 + 1], acc[mt][nt][3] + bb1);
        }
    }
}

// ---------------- LSTM cell update + zero gates + reset argmax ----------------
__global__ void k_update() {
    int idx = blockIdx.x * blockDim.x + threadIdx.x;
    if (idx < B * HID) {
        int b = idx / HID;
        int j = idx - b * HID;
        float* gr = &g_gates[b * GATES];
        float gi = gr[j];
        float gf = gr[HID + j];
        float gg = gr[2 * HID + j];
        float go = gr[3 * HID + j];
        gr[j] = 0.f;
        gr[HID + j] = 0.f;
        gr[2 * HID + j] = 0.f;
        gr[3 * HID + j] = 0.f;
        float iv = 1.f / (1.f + expf(-gi));
        float fv = 1.f / (1.f + expf(-gf));
        float gv = tanhf(gg);
        float ov = 1.f / (1.f + expf(-go));
        float c = fv * g_c[idx] + iv * gv;
        float h = ov * tanhf(c);
        g_c[idx] = c;
        g_h[idx] = h;
        split2(h, &G_HHI[idx], &G_HLO[idx]);
    }
    if (idx < B) { g_key[idx] = 0ull; }
}

__global__ void k_final(float* __restrict__ out) {
    int idx = blockIdx.x * blockDim.x + threadIdx.x;
    if (idx < B * HID) {
        out[idx]           = g_h[idx];
        out[B * HID + idx] = g_c[idx];
    }
}

extern "C" void kernel_launch(void* const* d_in, const int* in_sizes, int n_in,
                              void* d_out, int out_size) {
    const float* emb   = (const float*)d_in[1];
    const float* W_ih  = (const float*)d_in[2];
    const float* W_hh  = (const float*)d_in[3];
    const float* b_ih  = (const float*)d_in[4];
    const float* b_hh  = (const float*)d_in[5];
    const float* W_out = (const float*)d_in[6];
    const float* b_out = (const float*)d_in[7];
    float* out = (float*)d_out;

    k_init<<<2048, 256>>>(W_ih, W_hh, b_ih, b_hh, W_out);

    const long long logitsSize = (long long)B * MAXLEN * VOCAB;
    for (int t = 0; t < MAXLEN; t++) {
        k_gates<<<dim3(GATES / 128, 8), 256>>>(emb);
        k_update<<<192, 256>>>();
        k_logits<<<(VOCAB + 191) / 192, 256>>>(b_out, out + (long long)t * VOCAB);
    }
    if ((long long)out_size >= logitsSize + 2LL * B * HID) {
        k_final<<<192, 256>>>(out + logitsSize);
    }
}

// round 7
// speedup vs baseline: 3.4150x; 1.0824x over previous
#include <cuda_runtime.h>
#include <cuda_bf16.h>
#include <cstdint>
#include <math.h>

#define B      64
#define HID    768
#define VOCAB  50257
#define MAXLEN 32
#define GATES  (4*HID)
#define KCAT   (2*HID)
#define SOS    1
#define OSTRIDE ((long long)MAXLEN*VOCAB)

typedef unsigned int u32;
typedef unsigned long long u64;

// ---------------- device-global state ----------------
__device__ float g_h[B*HID];
__device__ float g_c[B*HID];
__device__ float g_gates[B*GATES];
__device__ float g_bgate[GATES];
__device__ u64   g_key[B];

__device__ uint4 g_WhiR[((size_t)VOCAB*HID)/8];
__device__ uint4 g_WloR[((size_t)VOCAB*HID)/8];
__device__ uint4 g_WchiR[((size_t)GATES*KCAT)/8];
__device__ uint4 g_WcloR[((size_t)GATES*KCAT)/8];
__device__ uint4 g_hhiR[(B*HID)/8];
__device__ uint4 g_hloR[(B*HID)/8];

#define G_WHI  ((__nv_bfloat16*)g_WhiR)
#define G_WLO  ((__nv_bfloat16*)g_WloR)
#define G_WCHI ((__nv_bfloat16*)g_WchiR)
#define G_WCLO ((__nv_bfloat16*)g_WcloR)
#define G_HHI  ((__nv_bfloat16*)g_hhiR)
#define G_HLO  ((__nv_bfloat16*)g_hloR)

__device__ __forceinline__ void split2(float v, __nv_bfloat16* hi, __nv_bfloat16* lo) {
    __nv_bfloat16 h = __float2bfloat16_rn(v);
    *hi = h;
    *lo = __float2bfloat16_rn(v - __bfloat162float(h));
}

__device__ __forceinline__ u64 packKey(float v, int n) {
    u32 u = __float_as_uint(v);
    if (u & 0x80000000u) { u = ~u; } else { u = u | 0x80000000u; }
    return (((u64)u) << 32) | (u64)(0xFFFFFFFFu - (u32)n);
}

__device__ __forceinline__ void ldsm4(u32* r, const __nv_bfloat16* p) {
    u32 a = (u32)__cvta_generic_to_shared(p);
    asm volatile("ldmatrix.sync.aligned.m8n8.x4.shared.b16 {%0,%1,%2,%3},[%4];"
                 : "=r"(r[0]), "=r"(r[1]), "=r"(r[2]), "=r"(r[3]) : "r"(a));
}

__device__ __forceinline__ void mma16816(float* d, const u32* a, u32 b0, u32 b1) {
    asm volatile("mma.sync.aligned.m16n8k16.row.col.f32.bf16.bf16.f32 "
                 "{%0,%1,%2,%3},{%4,%5,%6,%7},{%8,%9},{%0,%1,%2,%3};"
                 : "+f"(d[0]), "+f"(d[1]), "+f"(d[2]), "+f"(d[3])
                 : "r"(a[0]), "r"(a[1]), "r"(a[2]), "r"(a[3]), "r"(b0), "r"(b1));
}

__device__ __forceinline__ void cp16(void* dst, const void* src) {
    u32 d = (u32)__cvta_generic_to_shared(dst);
    asm volatile("cp.async.cg.shared.global [%0], [%1], 16;\n" :: "r"(d), "l"(src));
}

// ---------------- init ----------------
__global__ void k_init(const float* __restrict__ W_ih, const float* __restrict__ W_hh,
                       const float* __restrict__ b_ih, const float* __restrict__ b_hh,
                       const float* __restrict__ W_out) {
    size_t tid = (size_t)blockIdx.x * blockDim.x + threadIdx.x;
    size_t stride = (size_t)gridDim.x * blockDim.x;
    for (size_t i = tid; i < (size_t)VOCAB * HID; i += stride) {
        split2(W_out[i], &G_WHI[i], &G_WLO[i]);
    }
    for (size_t i = tid; i < (size_t)GATES * KCAT; i += stride) {
        int j = (int)(i / KCAT);
        int k = (int)(i - (size_t)j * KCAT);
        float v;
        if (k < HID) { v = W_ih[(size_t)j * HID + k]; }
        else         { v = W_hh[(size_t)j * HID + (k - HID)]; }
        split2(v, &G_WCHI[i], &G_WCLO[i]);
    }
    for (size_t i = tid; i < GATES; i += stride) { g_bgate[i] = b_ih[i] + b_hh[i]; }
    for (size_t i = tid; i < B * HID; i += stride) { g_h[i] = 0.f; g_c[i] = 0.f; }
    for (size_t i = tid; i < (size_t)B * GATES; i += stride) { g_gates[i] = 0.f; }
    if (tid < B) { g_key[tid] = (u64)(0xFFFFFFFFu - (u32)SOS); }
}

// ---------------- logits: C[64][VOCAB] = h @ W_out^T + b, fused argmax ----------------
// Block tile M64 x N128, 3-stage cp.async pipeline, both operands via ldmatrix.
// smem/stage: X 2x64x80B + W 2x128x80B = 30720B ; 3 stages = 92160B dynamic.
__global__ void __launch_bounds__(256, 2) k_logits(const float* __restrict__ bias,
                                                   float* __restrict__ outStep) {
    extern __shared__ uint4 Sm4[];
    __shared__ u64 skey[64];
    const __nv_bfloat16* Sm = (const __nv_bfloat16*)Sm4;

    int tid = threadIdx.x;
    int w = tid >> 5;
    int l = tid & 31;
    int wm = w >> 2;                   // 0..1 (m32 tile)
    int wn = w & 3;                    // 0..3 (n32 tile)
    int nbase = blockIdx.x * 128;
    if (tid < 64) { skey[tid] = 0ull; }

    int xrow = tid >> 2;               // cp.async coords
    int xcol = tid & 3;
    int sub = l >> 3;
    int arow = (sub & 1) * 8 + (l & 7);
    int acolo = (sub >> 1) * 8;
    int brow = (sub >> 1) * 8 + (l & 7);
    int bcolo = (sub & 1) * 8;

    float acc[2][4][4];
    #pragma unroll
    for (int i = 0; i < 2; i++) {
        #pragma unroll
        for (int j = 0; j < 4; j++) {
            #pragma unroll
            for (int q = 0; q < 4; q++) { acc[i][j][q] = 0.f; }
        }
    }

    // ---- prefetch chunks 0,1 ----
    #pragma unroll
    for (int c = 0; c < 2; c++) {
        int s = c;
        int kc = c * 32;
        cp16(&Sm4[s * 1920 + xrow * 5 + xcol],       &G_HHI[xrow * HID + kc + xcol * 8]);
        cp16(&Sm4[s * 1920 + 320 + xrow * 5 + xcol], &G_HLO[xrow * HID + kc + xcol * 8]);
        #pragma unroll
        for (int j = 0; j < 2; j++) {
            int row = (tid >> 2) + j * 64;
            int n = nbase + row;
            if (n > VOCAB - 1) { n = VOCAB - 1; }
            cp16(&Sm4[s * 1920 + 640 + row * 5 + xcol],
                 &G_WHI[(size_t)n * HID + kc + xcol * 8]);
            cp16(&Sm4[s * 1920 + 1280 + row * 5 + xcol],
                 &G_WLO[(size_t)n * HID + kc + xcol * 8]);
        }
        asm volatile("cp.async.commit_group;\n");
    }

    #pragma unroll 1
    for (int c = 0; c < 24; c++) {
        // prefetch chunk c+2 into stage (c+2)%3 (stage of chunk c-1, already consumed)
        if (c + 2 < 24) {
            int s = (c + 2) % 3;
            int kc = (c + 2) * 32;
            cp16(&Sm4[s * 1920 + xrow * 5 + xcol],       &G_HHI[xrow * HID + kc + xcol * 8]);
            cp16(&Sm4[s * 1920 + 320 + xrow * 5 + xcol], &G_HLO[xrow * HID + kc + xcol * 8]);
            #pragma unroll
            for (int j = 0; j < 2; j++) {
                int row = (tid >> 2) + j * 64;
                int n = nbase + row;
                if (n > VOCAB - 1) { n = VOCAB - 1; }
                cp16(&Sm4[s * 1920 + 640 + row * 5 + xcol],
                     &G_WHI[(size_t)n * HID + kc + xcol * 8]);
                cp16(&Sm4[s * 1920 + 1280 + row * 5 + xcol],
                     &G_WLO[(size_t)n * HID + kc + xcol * 8]);
            }
            asm volatile("cp.async.commit_group;\n");
        }
        // wait for chunk c
        if (c < 22) { asm volatile("cp.async.wait_group 2;\n"); }
        else if (c < 23) { asm volatile("cp.async.wait_group 1;\n"); }
        else { asm volatile("cp.async.wait_group 0;\n"); }
        __syncthreads();

        int s = c % 3;
        const __nv_bfloat16* Xb = Sm + s * 15360;
        const __nv_bfloat16* Wb = Sm + s * 15360 + 5120;
        #pragma unroll
        for (int kk = 0; kk < 2; kk++) {
            int kb = kk * 16;
            u32 ah[2][4];
            u32 al[2][4];
            #pragma unroll
            for (int mt = 0; mt < 2; mt++) {
                int r = wm * 32 + mt * 16 + arow;
                ldsm4(ah[mt], Xb + r * 40 + kb + acolo);
                ldsm4(al[mt], Xb + 2560 + r * 40 + kb + acolo);
            }
            u32 bh[2][4];
            u32 bl[2][4];
            #pragma unroll
            for (int ntp = 0; ntp < 2; ntp++) {
                int r = wn * 32 + ntp * 16 + brow;
                ldsm4(bh[ntp], Wb + r * 40 + kb + bcolo);
                ldsm4(bl[ntp], Wb + 5120 + r * 40 + kb + bcolo);
            }
            #pragma unroll
            for (int nt = 0; nt < 4; nt++) {
                int ntp = nt >> 1;
                int hf = (nt & 1) * 2;
                u32 h0 = bh[ntp][hf];
                u32 h1 = bh[ntp][hf + 1];
                u32 lo0 = bl[ntp][hf];
                u32 lo1 = bl[ntp][hf + 1];
                #pragma unroll
                for (int mt = 0; mt < 2; mt++) {
                    mma16816(acc[mt][nt], ah[mt], h0, h1);
                    mma16816(acc[mt][nt], ah[mt], lo0, lo1);
                    mma16816(acc[mt][nt], al[mt], h0, h1);
                }
            }
        }
        __syncthreads();
    }

    // epilogue: bias + store + argmax keys
    #pragma unroll
    for (int mt = 0; mt < 2; mt++) {
        int r = wm * 32 + mt * 16 + (l >> 2);
        u64 k0 = 0ull;
        u64 k1 = 0ull;
        #pragma unroll
        for (int nt = 0; nt < 4; nt++) {
            int c0 = nbase + wn * 32 + nt * 8 + (l & 3) * 2;
            if (c0 + 1 < VOCAB) {
                const float2* bp = reinterpret_cast<const float2*>(&bias[c0]);
                float2 bb = bp[0];
                float v0 = acc[mt][nt][0] + bb.x;
                float v1 = acc[mt][nt][1] + bb.y;
                float v2 = acc[mt][nt][2] + bb.x;
                float v3 = acc[mt][nt][3] + bb.y;
                outStep[(long long)r * OSTRIDE + c0]           = v0;
                outStep[(long long)r * OSTRIDE + c0 + 1]       = v1;
                outStep[(long long)(r + 8) * OSTRIDE + c0]     = v2;
                outStep[(long long)(r + 8) * OSTRIDE + c0 + 1] = v3;
                u64 t;
                t = packKey(v0, c0);     if (t > k0) { k0 = t; }
                t = packKey(v1, c0 + 1); if (t > k0) { k0 = t; }
                t = packKey(v2, c0);     if (t > k1) { k1 = t; }
                t = packKey(v3, c0 + 1); if (t > k1) { k1 = t; }
            } else if (c0 < VOCAB) {
                float bb = bias[c0];
                float v0 = acc[mt][nt][0] + bb;
                float v2 = acc[mt][nt][2] + bb;
                outStep[(long long)r * OSTRIDE + c0]       = v0;
                outStep[(long long)(r + 8) * OSTRIDE + c0] = v2;
                u64 t;
                t = packKey(v0, c0); if (t > k0) { k0 = t; }
                t = packKey(v2, c0); if (t > k1) { k1 = t; }
            }
        }
        #pragma unroll
        for (int s = 1; s <= 2; s <<= 1) {
            u64 o0 = __shfl_xor_sync(0xFFFFFFFFu, k0, s);
            u64 o1 = __shfl_xor_sync(0xFFFFFFFFu, k1, s);
            if (o0 > k0) { k0 = o0; }
            if (o1 > k1) { k1 = o1; }
        }
        if ((l & 3) == 0) {
            atomicMax(&skey[r], k0);
            atomicMax(&skey[r + 8], k1);
        }
    }
    __syncthreads();
    if (tid < 64) {
        if (skey[tid] != 0ull) { atomicMax(&g_key[tid], skey[tid]); }
    }
}

// ================= gates GEMM helpers (nt=2) =================
__device__ __forceinline__ void loadw2(u32 (&wb)[2][2][4], const u32* Whi32, const u32* Wlo32,
                                       const size_t (&wrow)[2], int kc) {
    int kw = kc >> 1;
    #pragma unroll
    for (int nt = 0; nt < 2; nt++) {
        const u32* ph = Whi32 + wrow[nt] + kw;
        const u32* pl = Wlo32 + wrow[nt] + kw;
        wb[nt][0][0] = ph[0]; wb[nt][0][1] = ph[4]; wb[nt][0][2] = ph[8]; wb[nt][0][3] = ph[12];
        wb[nt][1][0] = pl[0]; wb[nt][1][1] = pl[4]; wb[nt][1][2] = pl[8]; wb[nt][1][3] = pl[12];
    }
}

__device__ __forceinline__ void do_chunk2(float (&acc)[4][2][4], const u32 (&wb)[2][2][4],
                                          const __nv_bfloat16* Xs, int stg, int arow, int acolo) {
    #pragma unroll
    for (int kk = 0; kk < 2; kk++) {
        int kb = kk * 16;
        u32 ahi[4][4];
        u32 alo[4][4];
        #pragma unroll
        for (int mt = 0; mt < 4; mt++) {
            ldsm4(ahi[mt], &Xs[(stg * 2 + 0) * 2560 + (mt * 16 + arow) * 40 + kb + acolo]);
            ldsm4(alo[mt], &Xs[(stg * 2 + 1) * 2560 + (mt * 16 + arow) * 40 + kb + acolo]);
        }
        #pragma unroll
        for (int nt = 0; nt < 2; nt++) {
            u32 bh0 = wb[nt][0][2 * kk];
            u32 bh1 = wb[nt][0][2 * kk + 1];
            u32 bl0 = wb[nt][1][2 * kk];
            u32 bl1 = wb[nt][1][2 * kk + 1];
            #pragma unroll
            for (int mt = 0; mt < 4; mt++) {
                mma16816(acc[mt][nt], ahi[mt], bh0, bh1);
                mma16816(acc[mt][nt], ahi[mt], bl0, bl1);
                mma16816(acc[mt][nt], alo[mt], bh0, bh1);
            }
        }
    }
}

__device__ __forceinline__ void gatherx(int lm, int lk, int kc, const float* __restrict__ emb,
                                        const int* stoks, uint4& xh, uint4& xl) {
    int k = kc + lk;
    const float* src;
    if (k < HID) { src = emb + (size_t)stoks[lm] * HID + k; }
    else         { src = g_h + lm * HID + (k - HID); }
    float4 f0 = *reinterpret_cast<const float4*>(src);
    float4 f1 = *reinterpret_cast<const float4*>(src + 4);
    float v[8] = {f0.x, f0.y, f0.z, f0.w, f1.x, f1.y, f1.z, f1.w};
    u32 hw[4];
    u32 lw[4];
    #pragma unroll
    for (int e = 0; e < 4; e++) {
        __nv_bfloat16 h0, l0, h1, l1;
        split2(v[2 * e], &h0, &l0);
        split2(v[2 * e + 1], &h1, &l1);
        __nv_bfloat162 hp;
        hp.x = h0; hp.y = h1;
        __nv_bfloat162 lp;
        lp.x = l0; lp.y = l1;
        hw[e] = *reinterpret_cast<u32*>(&hp);
        lw[e] = *reinterpret_cast<u32*>(&lp);
    }
    xh = make_uint4(hw[0], hw[1], hw[2], hw[3]);
    xl = make_uint4(lw[0], lw[1], lw[2], lw[3]);
}

// ---------------- gates: g_gates[64][3072] += [emb|h] @ Wcat^T (+b on split 0) ----------------
__global__ void __launch_bounds__(256, 1) k_gates(const float* __restrict__ emb) {
    __shared__ uint4 XsRaw[1280];
    __shared__ int stoks[64];
    const __nv_bfloat16* Xs = (const __nv_bfloat16*)XsRaw;

    int tid = threadIdx.x;
    int w = tid >> 5;
    int l = tid & 31;
    int nwarp = blockIdx.x * 128 + w * 16;
    int kBegin = blockIdx.y * 192;

    if (tid < 64) {
        stoks[tid] = (int)(0xFFFFFFFFu - (u32)(g_key[tid] & 0xFFFFFFFFull));
    }
    __syncthreads();

    int lm = tid >> 2;
    int lk = (tid & 3) * 8;
    int sub = l >> 3;
    int arow = (sub & 1) * 8 + (l & 7);
    int acolo = (sub >> 1) * 8;

    const u32* Whi32 = (const u32*)g_WchiR;
    const u32* Wlo32 = (const u32*)g_WcloR;
    size_t wrow[2];
    #pragma unroll
    for (int nt = 0; nt < 2; nt++) {
        int n = nwarp + nt * 8 + (l >> 2);
        wrow[nt] = (size_t)n * (KCAT / 2) + (l & 3);
    }

    float acc[4][2][4];
    #pragma unroll
    for (int i = 0; i < 4; i++) {
        #pragma unroll
        for (int j = 0; j < 2; j++) {
            #pragma unroll
            for (int q = 0; q < 4; q++) { acc[i][j][q] = 0.f; }
        }
    }

    u32 wa[2][2][4];
    u32 wb[2][2][4];
    int sidx = lm * 5 + (lk >> 3);

    {
        uint4 xh0, xl0;
        gatherx(lm, lk, kBegin, emb, stoks, xh0, xl0);
        XsRaw[0 * 320 + sidx] = xh0;
        XsRaw[1 * 320 + sidx] = xl0;
    }
    loadw2(wa, Whi32, Wlo32, wrow, kBegin);
    __syncthreads();

    #pragma unroll 1
    for (int it = 0; it < 6; it += 2) {
        int kn1 = kBegin + (it + 1) * 32;
        uint4 xh1, xl1;
        gatherx(lm, lk, kn1, emb, stoks, xh1, xl1);
        loadw2(wb, Whi32, Wlo32, wrow, kn1);
        do_chunk2(acc, wa, Xs, 0, arow, acolo);
        XsRaw[2 * 320 + sidx] = xh1;
        XsRaw[3 * 320 + sidx] = xl1;
        __syncthreads();

        int kn2 = (it < 4) ? kBegin + (it + 2) * 32 : kBegin + 160;
        uint4 xh2, xl2;
        gatherx(lm, lk, kn2, emb, stoks, xh2, xl2);
        loadw2(wa, Whi32, Wlo32, wrow, kn2);
        do_chunk2(acc, wb, Xs, 1, arow, acolo);
        XsRaw[0 * 320 + sidx] = xh2;
        XsRaw[1 * 320 + sidx] = xl2;
        __syncthreads();
    }

    bool ab = (blockIdx.y == 0);
    #pragma unroll
    for (int mt = 0; mt < 4; mt++) {
        int r = mt * 16 + (l >> 2);
        #pragma unroll
        for (int nt = 0; nt < 2; nt++) {
            int c0 = nwarp + nt * 8 + (l & 3) * 2;
            float bb0 = 0.f;
            float bb1 = 0.f;
            if (ab) { bb0 = g_bgate[c0]; bb1 = g_bgate[c0 + 1]; }
            atomicAdd(&g_gates[r * GATES + c0],           acc[mt][nt][0] + bb0);
            atomicAdd(&g_gates[r * GATES + c0 + 1],       acc[mt][nt][1] + bb1);
            atomicAdd(&g_gates[(r + 8) * GATES + c0],     acc[mt][nt][2] + bb0);
            atomicAdd(&g_gates[(r + 8) * GATES + c0 + 1], acc[mt][nt][3] + bb1);
        }
    }
}

// ---------------- LSTM cell update + zero gates + reset argmax ----------------
__global__ void k_update() {
    int idx = blockIdx.x * blockDim.x + threadIdx.x;
    if (idx < B * HID) {
        int b = idx / HID;
        int j = idx - b * HID;
        float* gr = &g_gates[b * GATES];
        float gi = gr[j];
        float gf = gr[HID + j];
        float gg = gr[2 * HID + j];
        float go = gr[3 * HID + j];
        gr[j] = 0.f;
        gr[HID + j] = 0.f;
        gr[2 * HID + j] = 0.f;
        gr[3 * HID + j] = 0.f;
        float iv = 1.f / (1.f + expf(-gi));
        float fv = 1.f / (1.f + expf(-gf));
        float gv = tanhf(gg);
        float ov = 1.f / (1.f + expf(-go));
        float c = fv * g_c[idx] + iv * gv;
        float h = ov * tanhf(c);
        g_c[idx] = c;
        g_h[idx] = h;
        split2(h, &G_HHI[idx], &G_HLO[idx]);
    }
    if (idx < B) { g_key[idx] = 0ull; }
}

__global__ void k_final(float* __restrict__ out) {
    int idx = blockIdx.x * blockDim.x + threadIdx.x;
    if (idx < B * HID) {
        out[idx]           = g_h[idx];
        out[B * HID + idx] = g_c[idx];
    }
}

extern "C" void kernel_launch(void* const* d_in, const int* in_sizes, int n_in,
                              void* d_out, int out_size) {
    const float* emb   = (const float*)d_in[1];
    const float* W_ih  = (const float*)d_in[2];
    const float* W_hh  = (const float*)d_in[3];
    const float* b_ih  = (const float*)d_in[4];
    const float* b_hh  = (const float*)d_in[5];
    const float* W_out = (const float*)d_in[6];
    const float* b_out = (const float*)d_in[7];
    float* out = (float*)d_out;

    static int attrDone = 0;
    if (!attrDone) {
        cudaFuncSetAttribute(k_logits, cudaFuncAttributeMaxDynamicSharedMemorySize, 92160);
        attrDone = 1;
    }

    k_init<<<2048, 256>>>(W_ih, W_hh, b_ih, b_hh, W_out);

    const long long logitsSize = (long long)B * MAXLEN * VOCAB;
    for (int t = 0; t < MAXLEN; t++) {
        k_gates<<<dim3(GATES / 128, 8), 256>>>(emb);
        k_update<<<192, 256>>>();
        k_logits<<<(VOCAB + 127) / 128, 256, 92160>>>(b_out, out + (long long)t * VOCAB);
    }
    if ((long long)out_size >= logitsSize + 2LL * B * HID) {
        k_final<<<192, 256>>>(out + logitsSize);
    }
}